// round 4
// baseline (speedup 1.0000x reference)
#include <cuda_runtime.h>
#include <cuda_bf16.h>
#include <cstdint>

// T=8 towers:  out[t] = cumsum_t( relu(x@W1+b1) @ W2 + b2 )
// x:[T,4096,1024] W1:[T,1024,2048] b1:[T,2048] W2:[T,2048,512] b2:[T,512]
//
// Harness compiles via compute_100 virtual arch -> tcgen05 PTX is rejected.
// So: sm_80-class tensor path (mma.sync.m16n8k16 bf16 + ldmatrix + cp.async),
// bf16x3 split precision (AhBh + AlBh + AhBl) for <1e-3 rel_err.

#define DIM_T 8
#define DIM_B 4096
#define DIM_I 1024
#define DIM_H 2048
#define DIM_O 512

// ---------------- scratch (device globals: allocation-guard-safe) ----------
__device__ __nv_bfloat16 g_xh[(size_t)DIM_T * DIM_B * DIM_I];
__device__ __nv_bfloat16 g_xl[(size_t)DIM_T * DIM_B * DIM_I];
__device__ __nv_bfloat16 g_w1h[(size_t)DIM_T * DIM_H * DIM_I];   // [T,N,K]
__device__ __nv_bfloat16 g_w1l[(size_t)DIM_T * DIM_H * DIM_I];
__device__ __nv_bfloat16 g_w2h[(size_t)DIM_T * DIM_O * DIM_H];   // [T,N,K]
__device__ __nv_bfloat16 g_w2l[(size_t)DIM_T * DIM_O * DIM_H];
__device__ __nv_bfloat16 g_hh[(size_t)DIM_T * DIM_B * DIM_H];
__device__ __nv_bfloat16 g_hl[(size_t)DIM_T * DIM_B * DIM_H];

// ---------------- PTX helpers ----------------------------------------------
__device__ __forceinline__ uint32_t smem_u32(const void* p) {
    uint32_t a;
    asm("{ .reg .u64 t; cvta.to.shared.u64 t, %1; cvt.u32.u64 %0, t; }" : "=r"(a) : "l"(p));
    return a;
}
#define CP_ASYNC16(dst, src) \
    asm volatile("cp.async.cg.shared.global [%0], [%1], 16;" :: "r"(dst), "l"(src))
#define CP_COMMIT() asm volatile("cp.async.commit_group;" ::: "memory")
#define CP_WAIT1()  asm volatile("cp.async.wait_group 1;" ::: "memory")
#define CP_WAIT0()  asm volatile("cp.async.wait_group 0;" ::: "memory")

#define LDMX4(r, addr) \
    asm volatile("ldmatrix.sync.aligned.m8n8.x4.shared.b16 {%0,%1,%2,%3}, [%4];" \
        : "=r"((r)[0]), "=r"((r)[1]), "=r"((r)[2]), "=r"((r)[3]) : "r"(addr))

#define MMA16816(c, a, b0, b1) \
    asm volatile("mma.sync.aligned.m16n8k16.row.col.f32.bf16.bf16.f32 " \
        "{%0,%1,%2,%3}, {%4,%5,%6,%7}, {%8,%9}, {%0,%1,%2,%3};" \
        : "+f"((c)[0]), "+f"((c)[1]), "+f"((c)[2]), "+f"((c)[3]) \
        : "r"((a)[0]), "r"((a)[1]), "r"((a)[2]), "r"((a)[3]), "r"(b0), "r"(b1))

// ---------------- SMEM layout (dynamic): 3 stages x 64KB --------------------
// stage: Ah[128x64] 16K | Al 16K | Bh[128x64] 16K | Bl 16K
#define TILE_BYTES  16384
#define STAGE_BYTES (4 * TILE_BYTES)
#define NSTAGE      3
#define SMEM_TOTAL  (NSTAGE * STAGE_BYTES)   // 196608

// ---------------------------------------------------------------------------
// bf16x3 mma.sync GEMM.  C tile 128x128 per CTA, 256 threads (8 warps, 2x4),
// warp tile 64x32, BK=64, XOR swizzle, cp.async 3-stage pipeline.
// A(hi/lo): [T,M,K] bf16 K-major.  B(hi/lo): [T,N,K] bf16 K-major.
// ---------------------------------------------------------------------------
template <bool RELU, bool SPLIT_OUT>
__global__ __launch_bounds__(256, 1)
void mma_gemm(const __nv_bfloat16* __restrict__ Ah, const __nv_bfloat16* __restrict__ Al,
              const __nv_bfloat16* __restrict__ Bh, const __nv_bfloat16* __restrict__ Bl,
              const float* __restrict__ bias,
              __nv_bfloat16* __restrict__ OutHi, __nv_bfloat16* __restrict__ OutLo,
              float* __restrict__ OutF,
              int M, int N, int K)
{
    extern __shared__ char smem[];
    __shared__ float bias_s[128];
    const uint32_t sb = smem_u32(smem);

    const int tid  = threadIdx.x;
    const int lane = tid & 31;
    const int wid  = tid >> 5;
    const int wm   = wid >> 2;      // 0..1  (64-row slab)
    const int wn   = wid & 3;       // 0..3  (32-col slab)

    const int t  = blockIdx.z;
    const int bx = blockIdx.x;      // N tile
    const int by = blockIdx.y;      // M tile
    const int nbase = bx * 128;

    if (tid < 128) bias_s[tid] = bias[(size_t)t * N + nbase + tid];

    const __nv_bfloat16* srcs[4] = {
        Ah + (size_t)t * M * K + (size_t)by * 128 * K,
        Al + (size_t)t * M * K + (size_t)by * 128 * K,
        Bh + (size_t)t * N * K + (size_t)nbase * K,
        Bl + (size_t)t * N * K + (size_t)nbase * K
    };

    // per-thread cp.async mapping: 4 vec16 per tile
    // v = j*256+tid ; row = v>>3 ; chunk16 = v&7 ; dst XOR-swizzled
    auto issue_stage = [&](int ci) {
        const uint32_t stg = sb + (uint32_t)(ci % NSTAGE) * STAGE_BYTES;
        const int k0 = ci << 6;
        #pragma unroll
        for (int ti = 0; ti < 4; ti++) {
            #pragma unroll
            for (int j = 0; j < 4; j++) {
                int v = j * 256 + tid;
                int r = v >> 3, c8 = v & 7;
                const void* src = srcs[ti] + (size_t)r * K + k0 + c8 * 8;
                uint32_t dst = stg + ti * TILE_BYTES + r * 128 +
                               (((c8 ^ (r & 7)) & 7) << 4);
                CP_ASYNC16(dst, src);
            }
        }
        CP_COMMIT();
    };

    // ldmatrix per-lane geometry
    const int a_row  = lane & 15;          // row within m16 tile
    const int a_ksel = lane >> 4;          // 0/1 -> k8 block
    const int b_row  = (lane & 7) | ((lane >> 4) << 3);  // row within n16 pair
    const int b_ksel = (lane >> 3) & 1;

    float acc[4][4][4];
    #pragma unroll
    for (int m = 0; m < 4; m++)
        #pragma unroll
        for (int n = 0; n < 4; n++)
            #pragma unroll
            for (int q = 0; q < 4; q++) acc[m][n][q] = 0.0f;

    const int nChunks = K >> 6;
    issue_stage(0);
    issue_stage(1);

    for (int ci = 0; ci < nChunks; ci++) {
        if (ci + 1 < nChunks) { CP_WAIT1(); } else { CP_WAIT0(); }
        __syncthreads();

        const uint32_t stg  = sb + (uint32_t)(ci % NSTAGE) * STAGE_BYTES;
        const uint32_t Ah_b = stg;
        const uint32_t Al_b = stg + TILE_BYTES;
        const uint32_t Bh_b = stg + 2 * TILE_BYTES;
        const uint32_t Bl_b = stg + 3 * TILE_BYTES;

        #pragma unroll
        for (int ks = 0; ks < 4; ks++) {
            uint32_t ahf[4][4], alf[4][4];
            #pragma unroll
            for (int m = 0; m < 4; m++) {
                int rowg = wm * 64 + m * 16 + a_row;
                uint32_t off = rowg * 128 +
                    ((((ks * 2 + a_ksel) ^ (rowg & 7)) & 7) << 4);
                LDMX4(ahf[m], Ah_b + off);
                LDMX4(alf[m], Al_b + off);
            }
            uint32_t bhf[2][4], blf[2][4];
            #pragma unroll
            for (int p = 0; p < 2; p++) {
                int rowg = wn * 32 + p * 16 + b_row;
                uint32_t off = rowg * 128 +
                    ((((ks * 2 + b_ksel) ^ (rowg & 7)) & 7) << 4);
                LDMX4(bhf[p], Bh_b + off);
                LDMX4(blf[p], Bl_b + off);
            }
            #pragma unroll
            for (int m = 0; m < 4; m++)
                #pragma unroll
                for (int n = 0; n < 4; n++) {
                    const int p = n >> 1, q = (n & 1) * 2;
                    MMA16816(acc[m][n], ahf[m], bhf[p][q], bhf[p][q + 1]);
                    MMA16816(acc[m][n], alf[m], bhf[p][q], bhf[p][q + 1]);
                    MMA16816(acc[m][n], ahf[m], blf[p][q], blf[p][q + 1]);
                }
        }
        __syncthreads();
        if (ci + 2 < nChunks) issue_stage(ci + 2);
    }

    // ---------------- epilogue ----------------
    #pragma unroll
    for (int m = 0; m < 4; m++) {
        #pragma unroll
        for (int n = 0; n < 4; n++) {
            const int r0   = by * 128 + wm * 64 + m * 16 + (lane >> 2);
            const int cloc = wn * 32 + n * 8 + (lane & 3) * 2;
            const float bv0 = bias_s[cloc], bv1 = bias_s[cloc + 1];
            #pragma unroll
            for (int hrow = 0; hrow < 2; hrow++) {
                float v0 = acc[m][n][hrow * 2 + 0] + bv0;
                float v1 = acc[m][n][hrow * 2 + 1] + bv1;
                if (RELU) { v0 = fmaxf(v0, 0.0f); v1 = fmaxf(v1, 0.0f); }
                const size_t o = (size_t)t * M * N +
                                 (size_t)(r0 + hrow * 8) * N + nbase + cloc;
                if (SPLIT_OUT) {
                    __nv_bfloat16 h0 = __float2bfloat16(v0);
                    __nv_bfloat16 h1 = __float2bfloat16(v1);
                    __nv_bfloat16 l0 = __float2bfloat16(v0 - __bfloat162float(h0));
                    __nv_bfloat16 l1 = __float2bfloat16(v1 - __bfloat162float(h1));
                    uint32_t hp = (uint32_t)*reinterpret_cast<uint16_t*>(&h0) |
                                  ((uint32_t)*reinterpret_cast<uint16_t*>(&h1) << 16);
                    uint32_t lp = (uint32_t)*reinterpret_cast<uint16_t*>(&l0) |
                                  ((uint32_t)*reinterpret_cast<uint16_t*>(&l1) << 16);
                    *reinterpret_cast<uint32_t*>(OutHi + o) = hp;
                    *reinterpret_cast<uint32_t*>(OutLo + o) = lp;
                } else {
                    float2 f2 = make_float2(v0, v1);
                    *reinterpret_cast<float2*>(OutF + o) = f2;
                }
            }
        }
    }
}

// ---------------- prep kernels ---------------------------------------------
__global__ void split_f32(const float4* __restrict__ in,
                          __nv_bfloat16* __restrict__ hi,
                          __nv_bfloat16* __restrict__ lo, int n4)
{
    int i = blockIdx.x * blockDim.x + threadIdx.x;
    if (i >= n4) return;
    float4 f = in[i];
    float v[4] = {f.x, f.y, f.z, f.w};
    __nv_bfloat16 h[4], l[4];
    #pragma unroll
    for (int k = 0; k < 4; k++) {
        h[k] = __float2bfloat16(v[k]);
        l[k] = __float2bfloat16(v[k] - __bfloat162float(h[k]));
    }
    reinterpret_cast<uint2*>(hi)[i] = *reinterpret_cast<const uint2*>(h);
    reinterpret_cast<uint2*>(lo)[i] = *reinterpret_cast<const uint2*>(l);
}

// W [T,K,N] fp32 -> Wt [T,N,K] bf16 hi/lo.  grid (N/32, K/32, T), block (32,8)
__global__ void trans_split(const float* __restrict__ W,
                            __nv_bfloat16* __restrict__ Th,
                            __nv_bfloat16* __restrict__ Tl, int K, int N)
{
    __shared__ float tile[32][33];
    const int t = blockIdx.z;
    const int n0 = blockIdx.x * 32, k0 = blockIdx.y * 32;
    const float* Wt = W + (size_t)t * K * N;
    for (int i = threadIdx.y; i < 32; i += 8)
        tile[i][threadIdx.x] = Wt[(size_t)(k0 + i) * N + n0 + threadIdx.x];
    __syncthreads();
    for (int i = threadIdx.y; i < 32; i += 8) {
        float v = tile[threadIdx.x][i];
        __nv_bfloat16 h = __float2bfloat16(v);
        __nv_bfloat16 l = __float2bfloat16(v - __bfloat162float(h));
        size_t o = (size_t)t * N * K + (size_t)(n0 + i) * K + k0 + threadIdx.x;
        Th[o] = h;
        Tl[o] = l;
    }
}

// in-place cumsum over tower axis
__global__ void cumsum_kernel(float4* __restrict__ out)
{
    constexpr int PER_T4 = DIM_B * DIM_O / 4;
    const int i = blockIdx.x * blockDim.x + threadIdx.x;
    if (i >= PER_T4) return;
    float4 acc = out[i];
    #pragma unroll
    for (int t = 1; t < DIM_T; t++) {
        float4 v = out[(size_t)t * PER_T4 + i];
        acc.x += v.x; acc.y += v.y; acc.z += v.z; acc.w += v.w;
        out[(size_t)t * PER_T4 + i] = acc;
    }
}

// ---------------- launch ----------------------------------------------------
extern "C" void kernel_launch(void* const* d_in, const int* in_sizes, int n_in,
                              void* d_out, int out_size)
{
    (void)in_sizes; (void)n_in; (void)out_size;
    const float* x  = (const float*)d_in[0];
    const float* W1 = (const float*)d_in[1];
    const float* b1 = (const float*)d_in[2];
    const float* W2 = (const float*)d_in[3];
    const float* b2 = (const float*)d_in[4];
    float* out = (float*)d_out;

    __nv_bfloat16 *xh, *xl, *w1h, *w1l, *w2h, *w2l, *hh, *hl;
    cudaGetSymbolAddress((void**)&xh,  g_xh);
    cudaGetSymbolAddress((void**)&xl,  g_xl);
    cudaGetSymbolAddress((void**)&w1h, g_w1h);
    cudaGetSymbolAddress((void**)&w1l, g_w1l);
    cudaGetSymbolAddress((void**)&w2h, g_w2h);
    cudaGetSymbolAddress((void**)&w2l, g_w2l);
    cudaGetSymbolAddress((void**)&hh,  g_hh);
    cudaGetSymbolAddress((void**)&hl,  g_hl);

    cudaFuncSetAttribute(mma_gemm<true, true>,
                         cudaFuncAttributeMaxDynamicSharedMemorySize, SMEM_TOTAL);
    cudaFuncSetAttribute(mma_gemm<false, false>,
                         cudaFuncAttributeMaxDynamicSharedMemorySize, SMEM_TOTAL);

    // prep: split x, transpose+split W1/W2
    {
        int n4 = DIM_T * DIM_B * DIM_I / 4;
        split_f32<<<(n4 + 255) / 256, 256>>>((const float4*)x, xh, xl, n4);
    }
    {
        dim3 g(DIM_H / 32, DIM_I / 32, DIM_T);
        trans_split<<<g, dim3(32, 8)>>>(W1, w1h, w1l, DIM_I, DIM_H);
    }
    {
        dim3 g(DIM_O / 32, DIM_H / 32, DIM_T);
        trans_split<<<g, dim3(32, 8)>>>(W2, w2h, w2l, DIM_H, DIM_O);
    }

    // GEMM1: h = relu(x@W1 + b1) -> bf16 hi/lo
    {
        dim3 grid(DIM_H / 128, DIM_B / 128, DIM_T);   // (16,32,8)
        mma_gemm<true, true><<<grid, 256, SMEM_TOTAL>>>(
            xh, xl, w1h, w1l, b1, hh, hl, nullptr, DIM_B, DIM_H, DIM_I);
    }
    // GEMM2: y = h@W2 + b2 -> fp32
    {
        dim3 grid(DIM_O / 128, DIM_B / 128, DIM_T);   // (4,32,8)
        mma_gemm<false, false><<<grid, 256, SMEM_TOTAL>>>(
            hh, hl, w2h, w2l, b2, nullptr, nullptr, out, DIM_B, DIM_O, DIM_H);
    }
    // cumsum over towers
    {
        constexpr int PER_T4 = DIM_B * DIM_O / 4;
        cumsum_kernel<<<(PER_T4 + 255) / 256, 256>>>((float4*)out);
    }
}

// round 7
// speedup vs baseline: 1.4055x; 1.4055x over previous
#include <cuda_runtime.h>
#include <cuda_fp16.h>
#include <cstdint>

// T=8 towers:  out[t] = cumsum_t( relu(x@W1+b1) @ W2 + b2 )
// x:[T,4096,1024] W1:[T,1024,2048] b1:[T,2048] W2:[T,2048,512] b2:[T,512]
//
// compute_100 virtual arch blocks tcgen05 -> use mma.sync.m16n8k16 fp16.
// Asymmetric split precision: A = Ah + Al (two fp16, 21 bits), B = fp16(B).
// Error ~2.8e-4 per GEMM (norm), ~4e-4 end-to-end vs 1e-3 threshold.

#define DIM_T 8
#define DIM_B 4096
#define DIM_I 1024
#define DIM_H 2048
#define DIM_O 512

// ---------------- scratch (device globals: allocation-guard-safe) ----------
__device__ __half g_xh[(size_t)DIM_T * DIM_B * DIM_I];
__device__ __half g_xl[(size_t)DIM_T * DIM_B * DIM_I];
__device__ __half g_w1h[(size_t)DIM_T * DIM_H * DIM_I];   // [T,N,K]
__device__ __half g_w2h[(size_t)DIM_T * DIM_O * DIM_H];   // [T,N,K]
__device__ __half g_hh[(size_t)DIM_T * DIM_B * DIM_H];
__device__ __half g_hl[(size_t)DIM_T * DIM_B * DIM_H];

// ---------------- PTX helpers ----------------------------------------------
__device__ __forceinline__ uint32_t smem_u32(const void* p) {
    uint32_t a;
    asm("{ .reg .u64 t; cvta.to.shared.u64 t, %1; cvt.u32.u64 %0, t; }" : "=r"(a) : "l"(p));
    return a;
}
#define CP_ASYNC16(dst, src) \
    asm volatile("cp.async.cg.shared.global [%0], [%1], 16;" :: "r"(dst), "l"(src))
#define CP_COMMIT() asm volatile("cp.async.commit_group;" ::: "memory")
#define CP_WAIT1()  asm volatile("cp.async.wait_group 1;" ::: "memory")
#define CP_WAIT0()  asm volatile("cp.async.wait_group 0;" ::: "memory")

#define LDMX4(r, addr) \
    asm volatile("ldmatrix.sync.aligned.m8n8.x4.shared.b16 {%0,%1,%2,%3}, [%4];" \
        : "=r"((r)[0]), "=r"((r)[1]), "=r"((r)[2]), "=r"((r)[3]) : "r"(addr))

#define MMA16816(c, a, b0, b1) \
    asm volatile("mma.sync.aligned.m16n8k16.row.col.f32.f16.f16.f32 " \
        "{%0,%1,%2,%3}, {%4,%5,%6,%7}, {%8,%9}, {%0,%1,%2,%3};" \
        : "+f"((c)[0]), "+f"((c)[1]), "+f"((c)[2]), "+f"((c)[3]) \
        : "r"((a)[0]), "r"((a)[1]), "r"((a)[2]), "r"((a)[3]), "r"(b0), "r"(b1))

// ---------------- SMEM: 3 stages x 64KB -------------------------------------
// stage: Ah[128x64] 16K | Al[128x64] 16K | Bh[256x64] 32K
#define A_TILE_BYTES 16384
#define B_TILE_BYTES 32768
#define STAGE_BYTES  (2 * A_TILE_BYTES + B_TILE_BYTES)   // 65536
#define OFF_AH 0
#define OFF_AL A_TILE_BYTES
#define OFF_BH (2 * A_TILE_BYTES)
#define NSTAGE 3
#define SMEM_TOTAL (NSTAGE * STAGE_BYTES)                 // 196608

// ---------------------------------------------------------------------------
// fp16x2 (A-split) mma.sync GEMM.  C tile 128x256 per CTA, 8 warps (2x4),
// warp tile 64x64, BK=64, XOR swizzle, cp.async 3-stage pipeline.
// A(hi/lo): [T,M,K] fp16 K-major.  B(hi): [T,N,K] fp16 K-major.
// ---------------------------------------------------------------------------
template <bool RELU, bool SPLIT_OUT>
__global__ __launch_bounds__(256, 1)
void mma_gemm(const __half* __restrict__ Ah, const __half* __restrict__ Al,
              const __half* __restrict__ Bh,
              const float* __restrict__ bias,
              __half* __restrict__ OutHi, __half* __restrict__ OutLo,
              float* __restrict__ OutF,
              int M, int N, int K)
{
    extern __shared__ char smem[];
    __shared__ float bias_s[256];
    const uint32_t sb = smem_u32(smem);

    const int tid  = threadIdx.x;
    const int lane = tid & 31;
    const int wid  = tid >> 5;
    const int wm   = wid >> 2;      // 0..1  (64-row slab)
    const int wn   = wid & 3;       // 0..3  (64-col slab)

    const int t  = blockIdx.z;
    const int bx = blockIdx.x;      // N tile (256 wide)
    const int by = blockIdx.y;      // M tile (128 tall)
    const int nbase = bx * 256;

    bias_s[tid] = bias[(size_t)t * N + nbase + tid];

    const __half* srcAh = Ah + (size_t)t * M * K + (size_t)by * 128 * K;
    const __half* srcAl = Al + (size_t)t * M * K + (size_t)by * 128 * K;
    const __half* srcB  = Bh + (size_t)t * N * K + (size_t)nbase * K;

    // cp.async one stage: A tiles 1024 vec16 each, B tile 2048 vec16.
    auto issue_stage = [&](int ci) {
        const uint32_t stg = sb + (uint32_t)(ci % NSTAGE) * STAGE_BYTES;
        const int k0 = ci << 6;
        #pragma unroll
        for (int j = 0; j < 4; j++) {               // Ah
            int v = j * 256 + tid;
            int r = v >> 3, c8 = v & 7;
            uint32_t dst = stg + OFF_AH + r * 128 + (((c8 ^ (r & 7)) & 7) << 4);
            CP_ASYNC16(dst, srcAh + (size_t)r * K + k0 + c8 * 8);
        }
        #pragma unroll
        for (int j = 0; j < 4; j++) {               // Al
            int v = j * 256 + tid;
            int r = v >> 3, c8 = v & 7;
            uint32_t dst = stg + OFF_AL + r * 128 + (((c8 ^ (r & 7)) & 7) << 4);
            CP_ASYNC16(dst, srcAl + (size_t)r * K + k0 + c8 * 8);
        }
        #pragma unroll
        for (int j = 0; j < 8; j++) {               // Bh (256 rows)
            int v = j * 256 + tid;
            int r = v >> 3, c8 = v & 7;
            uint32_t dst = stg + OFF_BH + r * 128 + (((c8 ^ (r & 7)) & 7) << 4);
            CP_ASYNC16(dst, srcB + (size_t)r * K + k0 + c8 * 8);
        }
        CP_COMMIT();
    };

    // ldmatrix per-lane geometry
    const int a_row  = lane & 15;
    const int a_ksel = lane >> 4;
    const int b_row  = (lane & 7) | ((lane >> 4) << 3);
    const int b_ksel = (lane >> 3) & 1;

    float acc[4][8][4];
    #pragma unroll
    for (int m = 0; m < 4; m++)
        #pragma unroll
        for (int n = 0; n < 8; n++)
            #pragma unroll
            for (int q = 0; q < 4; q++) acc[m][n][q] = 0.0f;

    const int nChunks = K >> 6;
    issue_stage(0);
    issue_stage(1);

    for (int ci = 0; ci < nChunks; ci++) {
        if (ci + 1 < nChunks) { CP_WAIT1(); } else { CP_WAIT0(); }
        __syncthreads();
        if (ci + 2 < nChunks) issue_stage(ci + 2);   // overlap with compute

        const uint32_t stg  = sb + (uint32_t)(ci % NSTAGE) * STAGE_BYTES;
        const uint32_t Ah_b = stg + OFF_AH;
        const uint32_t Al_b = stg + OFF_AL;
        const uint32_t Bh_b = stg + OFF_BH;

        #pragma unroll
        for (int ks = 0; ks < 4; ks++) {
            uint32_t ahf[4][4], alf[4][4];
            #pragma unroll
            for (int m = 0; m < 4; m++) {
                int rowg = wm * 64 + m * 16 + a_row;
                uint32_t off = rowg * 128 +
                    ((((ks * 2 + a_ksel) ^ (rowg & 7)) & 7) << 4);
                LDMX4(ahf[m], Ah_b + off);
                LDMX4(alf[m], Al_b + off);
            }
            uint32_t bhf[4][4];
            #pragma unroll
            for (int p = 0; p < 4; p++) {
                int rowg = wn * 64 + p * 16 + b_row;
                uint32_t off = rowg * 128 +
                    ((((ks * 2 + b_ksel) ^ (rowg & 7)) & 7) << 4);
                LDMX4(bhf[p], Bh_b + off);
            }
            #pragma unroll
            for (int m = 0; m < 4; m++)
                #pragma unroll
                for (int n = 0; n < 8; n++) {
                    const int p = n >> 1, q = (n & 1) * 2;
                    MMA16816(acc[m][n], ahf[m], bhf[p][q], bhf[p][q + 1]);
                    MMA16816(acc[m][n], alf[m], bhf[p][q], bhf[p][q + 1]);
                }
        }
        __syncthreads();
    }

    // ---------------- epilogue ----------------
    #pragma unroll
    for (int m = 0; m < 4; m++) {
        #pragma unroll
        for (int n = 0; n < 8; n++) {
            const int r0   = by * 128 + wm * 64 + m * 16 + (lane >> 2);
            const int cloc = wn * 64 + n * 8 + (lane & 3) * 2;
            const float bv0 = bias_s[cloc], bv1 = bias_s[cloc + 1];
            #pragma unroll
            for (int hrow = 0; hrow < 2; hrow++) {
                float v0 = acc[m][n][hrow * 2 + 0] + bv0;
                float v1 = acc[m][n][hrow * 2 + 1] + bv1;
                if (RELU) { v0 = fmaxf(v0, 0.0f); v1 = fmaxf(v1, 0.0f); }
                const size_t o = (size_t)t * M * N +
                                 (size_t)(r0 + hrow * 8) * N + nbase + cloc;
                if (SPLIT_OUT) {
                    __half h0 = __float2half(v0);
                    __half h1 = __float2half(v1);
                    __half l0 = __float2half(v0 - __half2float(h0));
                    __half l1 = __float2half(v1 - __half2float(h1));
                    uint32_t hp = (uint32_t)*reinterpret_cast<uint16_t*>(&h0) |
                                  ((uint32_t)*reinterpret_cast<uint16_t*>(&h1) << 16);
                    uint32_t lp = (uint32_t)*reinterpret_cast<uint16_t*>(&l0) |
                                  ((uint32_t)*reinterpret_cast<uint16_t*>(&l1) << 16);
                    *reinterpret_cast<uint32_t*>(OutHi + o) = hp;
                    *reinterpret_cast<uint32_t*>(OutLo + o) = lp;
                } else {
                    *reinterpret_cast<float2*>(OutF + o) = make_float2(v0, v1);
                }
            }
        }
    }
}

// ---------------- prep kernels ---------------------------------------------
__global__ void split_f32(const float4* __restrict__ in,
                          __half* __restrict__ hi,
                          __half* __restrict__ lo, int n4)
{
    int i = blockIdx.x * blockDim.x + threadIdx.x;
    if (i >= n4) return;
    float4 f = in[i];
    float v[4] = {f.x, f.y, f.z, f.w};
    __half h[4], l[4];
    #pragma unroll
    for (int k = 0; k < 4; k++) {
        h[k] = __float2half(v[k]);
        l[k] = __float2half(v[k] - __half2float(h[k]));
    }
    reinterpret_cast<uint2*>(hi)[i] = *reinterpret_cast<const uint2*>(h);
    reinterpret_cast<uint2*>(lo)[i] = *reinterpret_cast<const uint2*>(l);
}

// W [T,K,N] fp32 -> Wt [T,N,K] fp16 (hi only).  grid (N/32, K/32, T), block (32,8)
__global__ void trans_round(const float* __restrict__ W,
                            __half* __restrict__ Th, int K, int N)
{
    __shared__ float tile[32][33];
    const int t = blockIdx.z;
    const int n0 = blockIdx.x * 32, k0 = blockIdx.y * 32;
    const float* Wt = W + (size_t)t * K * N;
    for (int i = threadIdx.y; i < 32; i += 8)
        tile[i][threadIdx.x] = Wt[(size_t)(k0 + i) * N + n0 + threadIdx.x];
    __syncthreads();
    for (int i = threadIdx.y; i < 32; i += 8) {
        size_t o = (size_t)t * N * K + (size_t)(n0 + i) * K + k0 + threadIdx.x;
        Th[o] = __float2half(tile[threadIdx.x][i]);
    }
}

// in-place cumsum over tower axis
__global__ void cumsum_kernel(float4* __restrict__ out)
{
    constexpr int PER_T4 = DIM_B * DIM_O / 4;
    const int i = blockIdx.x * blockDim.x + threadIdx.x;
    if (i >= PER_T4) return;
    float4 acc = out[i];
    #pragma unroll
    for (int t = 1; t < DIM_T; t++) {
        float4 v = out[(size_t)t * PER_T4 + i];
        acc.x += v.x; acc.y += v.y; acc.z += v.z; acc.w += v.w;
        out[(size_t)t * PER_T4 + i] = acc;
    }
}

// ---------------- launch ----------------------------------------------------
extern "C" void kernel_launch(void* const* d_in, const int* in_sizes, int n_in,
                              void* d_out, int out_size)
{
    (void)in_sizes; (void)n_in; (void)out_size;
    const float* x  = (const float*)d_in[0];
    const float* W1 = (const float*)d_in[1];
    const float* b1 = (const float*)d_in[2];
    const float* W2 = (const float*)d_in[3];
    const float* b2 = (const float*)d_in[4];
    float* out = (float*)d_out;

    __half *xh, *xl, *w1h, *w2h, *hh, *hl;
    cudaGetSymbolAddress((void**)&xh,  g_xh);
    cudaGetSymbolAddress((void**)&xl,  g_xl);
    cudaGetSymbolAddress((void**)&w1h, g_w1h);
    cudaGetSymbolAddress((void**)&w2h, g_w2h);
    cudaGetSymbolAddress((void**)&hh,  g_hh);
    cudaGetSymbolAddress((void**)&hl,  g_hl);

    cudaFuncSetAttribute(mma_gemm<true, true>,
                         cudaFuncAttributeMaxDynamicSharedMemorySize, SMEM_TOTAL);
    cudaFuncSetAttribute(mma_gemm<false, false>,
                         cudaFuncAttributeMaxDynamicSharedMemorySize, SMEM_TOTAL);

    // prep
    {
        int n4 = DIM_T * DIM_B * DIM_I / 4;
        split_f32<<<(n4 + 255) / 256, 256>>>((const float4*)x, xh, xl, n4);
    }
    {
        dim3 g(DIM_H / 32, DIM_I / 32, DIM_T);
        trans_round<<<g, dim3(32, 8)>>>(W1, w1h, DIM_I, DIM_H);
    }
    {
        dim3 g(DIM_O / 32, DIM_H / 32, DIM_T);
        trans_round<<<g, dim3(32, 8)>>>(W2, w2h, DIM_H, DIM_O);
    }

    // GEMM1: h = relu(x@W1 + b1) -> fp16 hi/lo
    {
        dim3 grid(DIM_H / 256, DIM_B / 128, DIM_T);   // (8,32,8)
        mma_gemm<true, true><<<grid, 256, SMEM_TOTAL>>>(
            xh, xl, w1h, b1, hh, hl, nullptr, DIM_B, DIM_H, DIM_I);
    }
    // GEMM2: y = h@W2 + b2 -> fp32
    {
        dim3 grid(DIM_O / 256, DIM_B / 128, DIM_T);   // (2,32,8)
        mma_gemm<false, false><<<grid, 256, SMEM_TOTAL>>>(
            hh, hl, w2h, b2, nullptr, nullptr, out, DIM_B, DIM_O, DIM_H);
    }
    // cumsum over towers
    {
        constexpr int PER_T4 = DIM_B * DIM_O / 4;
        cumsum_kernel<<<(PER_T4 + 255) / 256, 256>>>((float4*)out);
    }
}